// round 6
// baseline (speedup 1.0000x reference)
#include <cuda_runtime.h>
#include <math.h>

// NTXentLoss: B=2048, P=16, N=128, D=512 (fp32).
// R6: minimize serialized prologue — single sync before streaming, positive
//     row folded into the row loop, ALL reductions deferred to epilogue.
//     128-thread blocks: 10 blocks/SM in staggered phases, 1.38 waves.

#define DDIM 512
#define D4 (DDIM / 4)        // 128 float4 per row
#define THREADS 128
#define NWARPS (THREADS / 32)   // 4
#define TEMP_INV 10.0f
#define COS_EPS 1e-8f

// scratch (no cudaMalloc allowed)
__device__ float g_loss[4096];
__device__ unsigned int g_count = 0;

__device__ __forceinline__ float warpReduceSum(float v) {
#pragma unroll
    for (int o = 16; o; o >>= 1) v += __shfl_down_sync(0xffffffffu, v, o);
    return v;
}

__device__ __forceinline__ float warpReduceMax(float v) {
#pragma unroll
    for (int o = 16; o; o >>= 1) v = fmaxf(v, __shfl_down_sync(0xffffffffu, v, o));
    return v;
}

// Result valid in thread 0 only. Caller must __syncthreads() between reuses of sbuf.
__device__ __forceinline__ float blockReduceSum(float v, float* sbuf) {
    int lane = threadIdx.x & 31, wid = threadIdx.x >> 5;
    v = warpReduceSum(v);
    if (lane == 0) sbuf[wid] = v;
    __syncthreads();
    v = (threadIdx.x < NWARPS) ? sbuf[threadIdx.x] : 0.0f;
    if (wid == 0) {
#pragma unroll
        for (int o = NWARPS / 2; o; o >>= 1) v += __shfl_down_sync(0xffffffffu, v, o);
    }
    return v;
}

__device__ __forceinline__ float blockReduceMax(float v, float* sbuf) {
    int lane = threadIdx.x & 31, wid = threadIdx.x >> 5;
    v = warpReduceMax(v);
    if (lane == 0) sbuf[wid] = v;
    __syncthreads();
    v = (threadIdx.x < NWARPS) ? sbuf[threadIdx.x] : -INFINITY;
    if (wid == 0) {
#pragma unroll
        for (int o = NWARPS / 2; o; o >>= 1) v = fmaxf(v, __shfl_down_sync(0xffffffffu, v, o));
    }
    return v;
}

__global__ void __launch_bounds__(THREADS)
ntxent_main_kernel(const float* __restrict__ target,
                   const float* __restrict__ positives,
                   const float* __restrict__ negatives,
                   const int* __restrict__ pos_idx,
                   const int* __restrict__ neg_mask,
                   float* __restrict__ out,
                   int B, int P, int N) {
    const int b = blockIdx.x;
    const int tid = threadIdx.x;
    const int lane = tid & 31;
    const int w = tid >> 5;

    __shared__ float4 s_tgt[D4];      // 2KB target row
    __shared__ float s_dot[132];      // raw dots: [0..M-1]=negs, [M]=pos
    __shared__ float s_q[132];        // raw squared norms
    __shared__ int   s_valid[132];    // compacted valid negative indices
    __shared__ int   s_wcnt[NWARPS];
    __shared__ float s_red[NWARPS];
    __shared__ float s_bcast[4];      // [0]=||t||, [1]=pos_sim, [2]=lse max
    __shared__ int   s_islast;

    // --- compact valid negative indices (deterministic prefix via ballot) ---
    int mvalid = 0;
    if (tid < N) mvalid = (neg_mask[(size_t)b * N + tid] != 0);
    unsigned bal = __ballot_sync(0xffffffffu, mvalid);
    if (lane == 0) s_wcnt[w] = __popc(bal);

    // --- load target row into SMEM; keep |t|^2 partial in a register ---
    float4 tv = ((const float4*)(target + (size_t)b * DDIM))[tid];
    s_tgt[tid] = tv;
    const float tq = tv.x * tv.x + tv.y * tv.y + tv.z * tv.z + tv.w * tv.w;

    const int pi = pos_idx[b];
    __syncthreads();   // SINGLE sync before streaming: s_tgt, s_wcnt ready

    int off = 0, M = 0;
#pragma unroll
    for (int j = 0; j < NWARPS; j++) {
        int c = s_wcnt[j];
        if (j < w) off += c;
        M += c;
    }
    if (mvalid) s_valid[off + __popc(bal & ((1u << lane) - 1u))] = tid;
    __syncwarp();

    // --- stream all rows (valid negatives + positive as row M) ---
    // NOTE: s_valid writes are warp-local visible? No — cross-warp. We need
    // them visible before other warps read. But each warp writes a disjoint
    // compacted range and reads arbitrary entries -> one more sync needed.
    __syncthreads();

    const float4* negb = (const float4*)(negatives + (size_t)b * (size_t)N * DDIM);
    const float4* posr = (const float4*)(positives + ((size_t)b * P + pi) * (size_t)DDIM);
    const int R = M + 1;

    for (int base = 2 * w; base < R; base += 2 * NWARPS) {
        const float4* v0 = (base < M) ? (negb + (size_t)s_valid[base] * D4) : posr;
        const bool has1 = (base + 1) < R;
        const float4* v1 = has1 ? ((base + 1 < M) ? (negb + (size_t)s_valid[base + 1] * D4) : posr)
                                : v0;
        float4 x0[4], x1[4];
#pragma unroll
        for (int k = 0; k < 4; k++) x0[k] = v0[lane + 32 * k];
#pragma unroll
        for (int k = 0; k < 4; k++) x1[k] = v1[lane + 32 * k];

        float d0 = 0.0f, q0 = 0.0f, d1 = 0.0f, q1 = 0.0f;
#pragma unroll
        for (int k = 0; k < 4; k++) {
            float4 t = s_tgt[lane + 32 * k];
            d0 = fmaf(x0[k].x, t.x, d0); d0 = fmaf(x0[k].y, t.y, d0);
            d0 = fmaf(x0[k].z, t.z, d0); d0 = fmaf(x0[k].w, t.w, d0);
            q0 = fmaf(x0[k].x, x0[k].x, q0); q0 = fmaf(x0[k].y, x0[k].y, q0);
            q0 = fmaf(x0[k].z, x0[k].z, q0); q0 = fmaf(x0[k].w, x0[k].w, q0);
            d1 = fmaf(x1[k].x, t.x, d1); d1 = fmaf(x1[k].y, t.y, d1);
            d1 = fmaf(x1[k].z, t.z, d1); d1 = fmaf(x1[k].w, t.w, d1);
            q1 = fmaf(x1[k].x, x1[k].x, q1); q1 = fmaf(x1[k].y, x1[k].y, q1);
            q1 = fmaf(x1[k].z, x1[k].z, q1); q1 = fmaf(x1[k].w, x1[k].w, q1);
        }
        d0 = warpReduceSum(d0); q0 = warpReduceSum(q0);
        d1 = warpReduceSum(d1); q1 = warpReduceSum(q1);
        if (lane == 0) {
            s_dot[base] = d0; s_q[base] = q0;
            if (has1) { s_dot[base + 1] = d1; s_q[base + 1] = q1; }
        }
    }
    __syncthreads();

    // --- epilogue: ||t||, sims, masked LSE ---
    float tsum = blockReduceSum(tq, s_red);
    if (tid == 0) s_bcast[0] = sqrtf(tsum);
    __syncthreads();
    const float tnorm = s_bcast[0];

    // per-thread logit (tid < M); positive handled by thread 0 separately
    float x = -INFINITY;
    if (tid < M)
        x = (s_dot[tid] / fmaxf(sqrtf(s_q[tid]) * tnorm, COS_EPS)) * TEMP_INV;
    const float pos_sim =
        (s_dot[M] / fmaxf(sqrtf(s_q[M]) * tnorm, COS_EPS)) * TEMP_INV;

    float m = blockReduceMax(fmaxf(x, pos_sim), s_red);
    if (tid == 0) s_bcast[2] = m;
    __syncthreads();
    m = s_bcast[2];
    float e = (x == -INFINITY) ? 0.0f : expf(x - m);
    if (tid == 0) e += expf(pos_sim - m);   // fold positive term
    __syncthreads();  // protect s_red reuse
    float S = blockReduceSum(e, s_red);

    // --- publish per-anchor loss; last block reduces the mean ---
    if (tid == 0) {
        g_loss[b] = logf(S) + m - pos_sim;
        __threadfence();
        unsigned int old = atomicAdd(&g_count, 1u);
        s_islast = (old == (unsigned int)(B - 1));
    }
    __syncthreads();
    if (s_islast) {
        __threadfence();
        float v = 0.0f;
        for (int i = tid; i < B; i += THREADS) v += g_loss[i];
        __syncthreads();  // s_red safe to reuse
        v = blockReduceSum(v, s_red);
        if (tid == 0) {
            out[0] = v / (float)B;
            g_count = 0;  // reset for next graph replay
        }
    }
}

extern "C" void kernel_launch(void* const* d_in, const int* in_sizes, int n_in,
                              void* d_out, int out_size) {
    const float* target = (const float*)d_in[0];
    const float* positives = (const float*)d_in[1];
    const float* negatives = (const float*)d_in[2];
    const int* pos_idx = (const int*)d_in[3];
    const int* neg_mask = (const int*)d_in[4];
    float* out = (float*)d_out;

    const int B = in_sizes[0] / DDIM;                 // 2048
    const int P = in_sizes[1] / in_sizes[0];          // 16
    const int N = in_sizes[2] / in_sizes[0];          // 128

    ntxent_main_kernel<<<B, THREADS>>>(target, positives, negatives, pos_idx,
                                       neg_mask, out, B, P, N);
}